// round 1
// baseline (speedup 1.0000x reference)
#include <cuda_runtime.h>

#define D 64
#define MAXN 151552           // >= 150000 nodes, padded
#define MAXE 3300000          // >= 3.2M directed edges
#define MAX_SCAN_BLOCKS 256   // ceil(MAXN/1024) = 148 <= 256

// ---- scratch (device globals; no allocation allowed) ----
__device__ int   g_deg[MAXN];
__device__ float g_dinv[MAXN];
__device__ int   g_rowptr[MAXN + 1];
__device__ int   g_fill[MAXN];
__device__ int   g_cols[MAXE];
__device__ float g_xa[(size_t)MAXN * D];
__device__ float g_xb[(size_t)MAXN * D];
__device__ float g_acc[(size_t)MAXN * D];
__device__ int   g_bsum[MAX_SCAN_BLOCKS];

// ---------------- CSR construction ----------------

__global__ void k_zero_deg(int n) {
    int i = blockIdx.x * blockDim.x + threadIdx.x;
    if (i < n) g_deg[i] = 0;
}

__global__ void k_count(const int* __restrict__ row, int E) {
    int i = blockIdx.x * blockDim.x + threadIdx.x;
    if (i < E) atomicAdd(&g_deg[row[i]], 1);
}

__global__ void k_dinv(int n) {
    int i = blockIdx.x * blockDim.x + threadIdx.x;
    if (i < n) {
        int d = g_deg[i];
        g_dinv[i] = (d > 0) ? rsqrtf((float)d) : 0.0f;
    }
}

// scan pass 1: per-1024-element tile sums (256 threads x 4 elems)
__global__ void k_scan1(int n) {
    __shared__ int s[256];
    int base = blockIdx.x * 1024 + threadIdx.x * 4;
    int sum = 0;
#pragma unroll
    for (int j = 0; j < 4; j++) {
        int idx = base + j;
        if (idx < n) sum += g_deg[idx];
    }
    s[threadIdx.x] = sum;
    __syncthreads();
    for (int o = 128; o > 0; o >>= 1) {
        if (threadIdx.x < o) s[threadIdx.x] += s[threadIdx.x + o];
        __syncthreads();
    }
    if (threadIdx.x == 0) g_bsum[blockIdx.x] = s[0];
}

// scan pass 2: exclusive scan of block sums (single block, nb <= 256)
__global__ void k_scan2(int nb) {
    __shared__ int s[256];
    int v = (threadIdx.x < nb) ? g_bsum[threadIdx.x] : 0;
    s[threadIdx.x] = v;
    __syncthreads();
    for (int o = 1; o < 256; o <<= 1) {
        int t = (threadIdx.x >= o) ? s[threadIdx.x - o] : 0;
        __syncthreads();
        s[threadIdx.x] += t;
        __syncthreads();
    }
    if (threadIdx.x < nb) g_bsum[threadIdx.x] = s[threadIdx.x] - v;  // exclusive
}

// scan pass 3: produce exclusive rowptr + fill cursors
__global__ void k_scan3(int n) {
    __shared__ int s[256];
    int base = blockIdx.x * 1024 + threadIdx.x * 4;
    int c[4];
    int tsum = 0;
#pragma unroll
    for (int j = 0; j < 4; j++) {
        int idx = base + j;
        c[j] = (idx < n) ? g_deg[idx] : 0;
        tsum += c[j];
    }
    s[threadIdx.x] = tsum;
    __syncthreads();
    for (int o = 1; o < 256; o <<= 1) {
        int t = (threadIdx.x >= o) ? s[threadIdx.x - o] : 0;
        __syncthreads();
        s[threadIdx.x] += t;
        __syncthreads();
    }
    int texcl = s[threadIdx.x] - tsum;
    int run = g_bsum[blockIdx.x] + texcl;
#pragma unroll
    for (int j = 0; j < 4; j++) {
        int idx = base + j;
        if (idx < n) {
            g_rowptr[idx] = run;
            g_fill[idx]   = run;
            run += c[j];
            if (idx == n - 1) g_rowptr[n] = run;
        }
    }
}

__global__ void k_scatter(const int* __restrict__ row,
                          const int* __restrict__ col, int E) {
    int i = blockIdx.x * blockDim.x + threadIdx.x;
    if (i < E) {
        int r = row[i];
        int pos = atomicAdd(&g_fill[r], 1);
        g_cols[pos] = col[i];
    }
}

// ---------------- feature init ----------------

__global__ void k_init(const float* __restrict__ ue,
                       const float* __restrict__ ie,
                       int nu_elems, int total_elems) {
    int i = blockIdx.x * blockDim.x + threadIdx.x;
    if (i < total_elems) {
        float v = (i < nu_elems) ? ue[i] : ie[i - nu_elems];
        g_xa[i]  = v;
        g_acc[i] = v;
    }
}

// ---------------- SpMM: warp per row, float2 lanes ----------------

__global__ void k_spmm(int sel, int n) {
    int warp = (blockIdx.x * blockDim.x + threadIdx.x) >> 5;
    int lane = threadIdx.x & 31;
    if (warp >= n) return;

    const float2* __restrict__ src =
        (const float2*)(sel ? g_xb : g_xa);
    float2* __restrict__ dst = (float2*)(sel ? g_xa : g_xb);

    int start = g_rowptr[warp];
    int end   = g_rowptr[warp + 1];

    float sx = 0.0f, sy = 0.0f;
    int e = start;
    // 4x unroll: batch col/dinv/x loads for MLP
    for (; e + 4 <= end; e += 4) {
        int c0 = __ldg(&g_cols[e + 0]);
        int c1 = __ldg(&g_cols[e + 1]);
        int c2 = __ldg(&g_cols[e + 2]);
        int c3 = __ldg(&g_cols[e + 3]);
        float d0 = __ldg(&g_dinv[c0]);
        float d1 = __ldg(&g_dinv[c1]);
        float d2 = __ldg(&g_dinv[c2]);
        float d3 = __ldg(&g_dinv[c3]);
        float2 v0 = __ldg(&src[c0 * 32 + lane]);
        float2 v1 = __ldg(&src[c1 * 32 + lane]);
        float2 v2 = __ldg(&src[c2 * 32 + lane]);
        float2 v3 = __ldg(&src[c3 * 32 + lane]);
        sx += d0 * v0.x + d1 * v1.x + d2 * v2.x + d3 * v3.x;
        sy += d0 * v0.y + d1 * v1.y + d2 * v2.y + d3 * v3.y;
    }
    for (; e < end; e++) {
        int c = __ldg(&g_cols[e]);
        float d = __ldg(&g_dinv[c]);
        float2 v = __ldg(&src[c * 32 + lane]);
        sx += d * v.x;
        sy += d * v.y;
    }

    float dr = g_dinv[warp];
    sx *= dr;
    sy *= dr;

    int o = warp * 32 + lane;
    dst[o] = make_float2(sx, sy);
    float2* accp = (float2*)g_acc;
    float2 a = accp[o];
    a.x += sx;
    a.y += sy;
    accp[o] = a;
}

// ---------------- scoring ----------------

__global__ void k_score(const int* __restrict__ uidx,
                        const int* __restrict__ iidx,
                        float* __restrict__ out, int B, int nu) {
    int warp = (blockIdx.x * blockDim.x + threadIdx.x) >> 5;
    int lane = threadIdx.x & 31;
    if (warp >= B) return;
    int u  = uidx[warp];
    int it = iidx[warp] + nu;
    const float2* a = (const float2*)g_acc;
    float2 au = __ldg(&a[u * 32 + lane]);
    float2 ai = __ldg(&a[it * 32 + lane]);
    float p = au.x * ai.x + au.y * ai.y;
#pragma unroll
    for (int o = 16; o > 0; o >>= 1)
        p += __shfl_xor_sync(0xffffffffu, p, o);
    if (lane == 0) out[warp] = p * (1.0f / 16.0f);  // /(L+1)^2 = /16
}

// ---------------- launch ----------------

extern "C" void kernel_launch(void* const* d_in, const int* in_sizes, int n_in,
                              void* d_out, int out_size) {
    const float* ue   = (const float*)d_in[0];
    const float* ie   = (const float*)d_in[1];
    const int*   erow = (const int*)d_in[2];
    const int*   ecol = (const int*)d_in[3];
    const int*   uidx = (const int*)d_in[4];
    const int*   iidx = (const int*)d_in[5];
    float* out = (float*)d_out;

    int nu = in_sizes[0] / D;
    int ni = in_sizes[1] / D;
    int N  = nu + ni;
    int E  = in_sizes[2];
    int B  = in_sizes[4];

    k_zero_deg<<<(N + 255) / 256, 256>>>(N);
    k_count<<<(E + 255) / 256, 256>>>(erow, E);
    k_dinv<<<(N + 255) / 256, 256>>>(N);

    int nb = (N + 1023) / 1024;
    k_scan1<<<nb, 256>>>(N);
    k_scan2<<<1, 256>>>(nb);
    k_scan3<<<nb, 256>>>(N);
    k_scatter<<<(E + 255) / 256, 256>>>(erow, ecol, E);

    int tot = N * D;
    k_init<<<(tot + 255) / 256, 256>>>(ue, ie, in_sizes[0], tot);

    // 3 propagation layers, ping-pong xa <-> xb, acc += each layer
    k_spmm<<<(N + 7) / 8, 256>>>(0, N);  // xa -> xb
    k_spmm<<<(N + 7) / 8, 256>>>(1, N);  // xb -> xa
    k_spmm<<<(N + 7) / 8, 256>>>(0, N);  // xa -> xb

    k_score<<<(B + 7) / 8, 256>>>(uidx, iidx, out, B, nu);
}